// round 12
// baseline (speedup 1.0000x reference)
#include <cuda_runtime.h>

#define WIDTH    512
#define HEIGHT   512
#define TH       64
#define TH_IN    (TH + 10)        // 74 input rows per strip
#define WPB      4                // warps per block (128 threads)
#define NBLK     1536             // 6144 warp-tasks / 4

#define C1v 1.0e-4f
#define C2v 9.0e-4f

// Gaussian(sigma=1.5, k=11) weights; compile-time indices -> FFMA-imm (rt=1).
#define DECL_KW \
    constexpr float KW[11] = { \
        0.00102838f, 0.00759876f, 0.03600078f, 0.10936081f, 0.21300554f, \
        0.26601173f, \
        0.21300554f, 0.10936081f, 0.03600078f, 0.00759876f, 0.00102838f }

__device__ float g_partial[NBLK];
__device__ int   g_count = 0;

struct Row { float2 mp, mt, hp, ht; };

__device__ __forceinline__ Row load_row(
    const float* __restrict__ P, const float* __restrict__ T,
    int r, int c0, int hcol, bool hval)
{
    Row v;
    v.mp = make_float2(0.f, 0.f); v.mt = make_float2(0.f, 0.f);
    v.hp = make_float2(0.f, 0.f); v.ht = make_float2(0.f, 0.f);
    if ((unsigned)r < (unsigned)HEIGHT) {       // warp-uniform branch
        const float* p = P + r * WIDTH;
        const float* t = T + r * WIDTH;
        v.mp = *(const float2*)(p + c0);
        v.mt = *(const float2*)(t + c0);
        if (hval) {                             // per-lane predicate
            v.hp = *(const float2*)(p + hcol);
            v.ht = *(const float2*)(t + hcol);
        }
    }
    return v;
}

__global__ void __launch_bounds__(128, 4)
ssim_main(const float* __restrict__ pred, const float* __restrict__ targ,
          float* __restrict__ out) {
    DECL_KW;
    // Warp-private staging: 76 float4 (e,d,e^2,d^2) entries per buffer:
    // [0..5] left pad (cols colbase-6..-1), [6..69] own 64 cols,
    // [70..75] right pad (cols colbase+64..+69). Double-buffered.
    __shared__ float4 sW[2][WPB][76];
    __shared__ float  wsum[WPB];
    __shared__ double dsh[128];
    __shared__ int    sIsLast;

    const int tid = threadIdx.x;
    const int w   = tid >> 5;
    const int l   = tid & 31;
    const int gw  = blockIdx.x * WPB + w;     // 0..6143, exact

    // decode: ch = gw/64, strip = (gw%64)/8, colstrip = gw%8
    const int ch      = gw >> 6;
    const int rem     = gw & 63;
    const int y0      = (rem >> 3) * TH;
    const int colbase = (rem & 7) << 6;
    const int c0      = colbase + 2 * l;      // owns cols c0, c0+1

    // halo: lanes 0..2 stage left pad (2 cols each), lanes 3..5 right pad
    int hcol = c0, hidx = 6 + 2 * l; bool hval = false;
    if (l < 3)      { hcol = colbase - 6 + 2 * l;        hidx = 2 * l;
                      hval = (colbase > 0); }
    else if (l < 6) { hcol = colbase + 64 + 2 * (l - 3); hidx = 70 + 2 * (l - 3);
                      hval = (colbase < WIDTH - 64); }
    const bool isHalo = (l < 6);

    const float* __restrict__ P = pred + (size_t)ch * (WIDTH * HEIGHT);
    const float* __restrict__ T = targ + (size_t)ch * (WIDTH * HEIGHT);

    // vertical rings: 2 pixels x 4 quantities x 11 rows = 88 regs
    float rE0[11], rD0[11], rE20[11], rD20[11];
    float rE1[11], rD1[11], rE21[11], rD21[11];
    float acc = 0.f;

    Row nxt = load_row(P, T, y0 - 5, c0, hcol, hval && isHalo);

    #pragma unroll 1
    for (int kc = 0; kc < TH_IN; kc += 11) {
        #pragma unroll
        for (int u = 0; u < 11; u++) {
            const int k = kc + u;
            if (k >= TH_IN) break;   // uniform

            const Row cur = nxt;
            // prefetch next row (one extra harmless row at the very end)
            nxt = load_row(P, T, y0 - 4 + k, c0, hcol, hval && isHalo);

            // stage (e, d, e^2, d^2) for own 2 cols (+ halo lanes)
            const int buf = k & 1;
            {
                const float e0 = cur.mp.x + cur.mt.x, d0 = cur.mp.x - cur.mt.x;
                const float e1 = cur.mp.y + cur.mt.y, d1 = cur.mp.y - cur.mt.y;
                sW[buf][w][6 + 2 * l] = make_float4(e0, d0, e0 * e0, d0 * d0);
                sW[buf][w][7 + 2 * l] = make_float4(e1, d1, e1 * e1, d1 * d1);
            }
            if (isHalo) {
                const float e0 = cur.hp.x + cur.ht.x, d0 = cur.hp.x - cur.ht.x;
                const float e1 = cur.hp.y + cur.ht.y, d1 = cur.hp.y - cur.ht.y;
                sW[buf][w][hidx]     = make_float4(e0, d0, e0 * e0, d0 * d0);
                sW[buf][w][hidx + 1] = make_float4(e1, d1, e1 * e1, d1 * d1);
            }
            __syncwarp();

            // horizontal conv: 12 LDS.128 shared by both pixels, 88 FFMA-imm
            float aE0 = 0.f, aD0 = 0.f, aE20 = 0.f, aD20 = 0.f;
            float aE1 = 0.f, aD1 = 0.f, aE21 = 0.f, aD21 = 0.f;
            #pragma unroll
            for (int j = 0; j < 12; j++) {
                const float4 v = sW[buf][w][2 * l + 1 + j];
                if (j < 11) {
                    aE0  = fmaf(v.x, KW[j], aE0);
                    aD0  = fmaf(v.y, KW[j], aD0);
                    aE20 = fmaf(v.z, KW[j], aE20);
                    aD20 = fmaf(v.w, KW[j], aD20);
                }
                if (j >= 1) {
                    aE1  = fmaf(v.x, KW[j - 1], aE1);
                    aD1  = fmaf(v.y, KW[j - 1], aD1);
                    aE21 = fmaf(v.z, KW[j - 1], aE21);
                    aD21 = fmaf(v.w, KW[j - 1], aD21);
                }
            }
            rE0[u] = aE0; rD0[u] = aD0; rE20[u] = aE20; rD20[u] = aD20;
            rE1[u] = aE1; rD1[u] = aD1; rE21[u] = aE21; rD21[u] = aD21;

            // vertical conv + SSIM once ring full (output row k-10)
            if (k >= 10) {
                float me0 = 0.f, md0 = 0.f, ce0 = 0.f, cd0 = 0.f;
                float me1 = 0.f, md1 = 0.f, ce1 = 0.f, cd1 = 0.f;
                #pragma unroll
                for (int i = 0; i < 11; i++) {
                    const int s = (u + 1 + i) % 11;
                    me0 = fmaf(rE0[s],  KW[i], me0);
                    md0 = fmaf(rD0[s],  KW[i], md0);
                    ce0 = fmaf(rE20[s], KW[i], ce0);
                    cd0 = fmaf(rD20[s], KW[i], cd0);
                    me1 = fmaf(rE1[s],  KW[i], me1);
                    md1 = fmaf(rD1[s],  KW[i], md1);
                    ce1 = fmaf(rE21[s], KW[i], ce1);
                    cd1 = fmaf(rD21[s], KW[i], cd1);
                }
                {
                    const float A  = me0 * me0, B = md0 * md0;
                    const float t1 = A - B,     t2 = A + B;
                    const float n1 = fmaf(0.5f, t1, C1v);
                    const float d1 = fmaf(0.5f, t2, C1v);
                    const float n2 = fmaf(0.5f, (ce0 - cd0) - t1, C2v);
                    const float d2 = fmaf(0.5f, (ce0 + cd0) - t2, C2v);
                    acc += __fdividef(n1 * n2, d1 * d2);
                }
                {
                    const float A  = me1 * me1, B = md1 * md1;
                    const float t1 = A - B,     t2 = A + B;
                    const float n1 = fmaf(0.5f, t1, C1v);
                    const float d1 = fmaf(0.5f, t2, C1v);
                    const float n2 = fmaf(0.5f, (ce1 - cd1) - t1, C2v);
                    const float d2 = fmaf(0.5f, (ce1 + cd1) - t2, C2v);
                    acc += __fdividef(n1 * n2, d1 * d2);
                }
            }
        }
    }

    // deterministic block reduction (one barrier at the end)
    #pragma unroll
    for (int o = 16; o > 0; o >>= 1)
        acc += __shfl_down_sync(0xffffffffu, acc, o);
    if (l == 0) wsum[w] = acc;
    __syncthreads();
    if (tid < 32) {
        float v = (l < WPB) ? wsum[l] : 0.f;
        v += __shfl_down_sync(0xffffffffu, v, 2);
        v += __shfl_down_sync(0xffffffffu, v, 1);
        if (l == 0)
            g_partial[blockIdx.x] = v;
    }

    // deterministic last-block final reduction (fp64, fixed order)
    if (tid == 0) {
        __threadfence();
        const int n = atomicAdd(&g_count, 1);
        sIsLast = (n == NBLK - 1);
    }
    __syncthreads();
    if (sIsLast) {
        __threadfence();
        double s = 0.0;
        for (int i = tid; i < NBLK; i += 128)
            s += (double)g_partial[i];
        dsh[tid] = s;
        __syncthreads();
        #pragma unroll 1
        for (int o = 64; o > 0; o >>= 1) {
            if (tid < o) dsh[tid] += dsh[tid + o];
            __syncthreads();
        }
        if (tid == 0) {
            out[0] = (float)(1.0 - dsh[0] / 25165824.0);  // 32*3*512*512
            g_count = 0;  // reset for next graph replay
        }
    }
}

extern "C" void kernel_launch(void* const* d_in, const int* in_sizes, int n_in,
                              void* d_out, int out_size) {
    const float* pred = (const float*)d_in[0];
    const float* targ = (const float*)d_in[1];
    ssim_main<<<NBLK, 128>>>(pred, targ, (float*)d_out);
}

// round 13
// speedup vs baseline: 1.2078x; 1.2078x over previous
#include <cuda_runtime.h>

#define WIDTH    512
#define HEIGHT   512
#define TH       64
#define TH_IN    (TH + 10)            // 74 input rows per strip
#define STRIPS   (HEIGHT / TH)        // 8
#define HALVES   2
#define CHANNELS 96                   // 32 * 3
#define NBLK     (HALVES * STRIPS * CHANNELS) // 1536

#define C1v 1.0e-4f
#define C2v 9.0e-4f

// Gaussian(sigma=1.5, k=11) weights; compile-time indices -> FFMA-imm (rt=1).
#define DECL_KW \
    constexpr float KW[11] = { \
        0.00102838f, 0.00759876f, 0.03600078f, 0.10936081f, 0.21300554f, \
        0.26601173f, \
        0.21300554f, 0.10936081f, 0.03600078f, 0.00759876f, 0.00102838f }

__device__ float g_partial[NBLK];
__device__ int   g_count = 0;

__global__ void __launch_bounds__(256, 4)
ssim_main(const float* __restrict__ pred, const float* __restrict__ targ,
          float* __restrict__ out) {
    DECL_KW;
    // Warp-private staging: 42 float4 (e, d, e^2, d^2) per warp per buffer
    // (32 own cols + 5 halo each side), double-buffered; only __syncwarp().
    // 16B lane stride -> conflict-free STS.128 / LDS.128.
    __shared__ float4 sW[2][8][44];
    __shared__ float  wsum[8];
    __shared__ double dsh[256];
    __shared__ int    sIsLast;

    const int tid  = threadIdx.x;
    const int w    = tid >> 5;
    const int l    = tid & 31;
    const int half  = blockIdx.x & 1;
    const int strip = blockIdx.x >> 1;
    const int ch    = blockIdx.y;
    const int y0    = strip * TH;
    const int colbase = half * 256 + w * 32;
    const int c0 = colbase + l;

    // halo assignment for lanes 0..9
    int hidx = 0, chalo = 0; bool hval = false;
    if (l < 5)       { chalo = colbase - 5 + l;  hidx = l;      hval = (chalo >= 0); }
    else if (l < 10) { chalo = colbase + 27 + l; hidx = 32 + l; hval = (chalo < WIDTH); }

    const float* __restrict__ P = pred + (size_t)ch * (WIDTH * HEIGHT);
    const float* __restrict__ T = targ + (size_t)ch * (WIDTH * HEIGHT);

    // vertical ring over 11 horizontal-conv result rows (scalar, 44 regs)
    float rE[11], rD[11], rE2[11], rD2[11];
    float acc = 0.f;

    // 1-deep prefetch
    float pN = 0.f, tN = 0.f, pHN = 0.f, tHN = 0.f;
    {
        const int r = y0 - 5;
        if ((unsigned)r < (unsigned)HEIGHT) {
            pN = P[r * WIDTH + c0];
            tN = T[r * WIDTH + c0];
            if (hval) { pHN = P[r * WIDTH + chalo]; tHN = T[r * WIDTH + chalo]; }
        }
    }

    // k = 0..TH_IN-1; ring slot = k % 11 (kc % 11 == 0 keeps it compile-time)
    #pragma unroll 1
    for (int kc = 0; kc < TH_IN; kc += 11) {
        #pragma unroll
        for (int u = 0; u < 11; u++) {
            const int k = kc + u;
            if (k >= TH_IN) break;   // uniform

            const float p = pN, t = tN, ph = pHN, th = tHN;
            if (k + 1 < TH_IN) {     // prefetch abs row y0-4+k
                const int r = y0 - 4 + k;
                if ((unsigned)r < (unsigned)HEIGHT) {
                    pN = P[r * WIDTH + c0];
                    tN = T[r * WIDTH + c0];
                    if (hval) { pHN = P[r * WIDTH + chalo]; tHN = T[r * WIDTH + chalo]; }
                    else      { pHN = 0.f; tHN = 0.f; }
                } else { pN = 0.f; tN = 0.f; pHN = 0.f; tHN = 0.f; }
            }

            // stage (e, d, e^2, d^2): squares computed ONCE here
            const int buf = k & 1;
            {
                const float e = p + t, d = p - t;
                sW[buf][w][5 + l] = make_float4(e, d, e * e, d * d);
            }
            if (l < 10) {
                const float e = ph + th, d = ph - th;
                sW[buf][w][hidx] = make_float4(e, d, e * e, d * d);
            }
            __syncwarp();

            // horizontal conv: 11 LDS.128 + 44 FFMA-imm (no per-tap FMULs)
            float hE = 0.f, hD = 0.f, hE2 = 0.f, hD2 = 0.f;
            #pragma unroll
            for (int i = 0; i < 11; i++) {
                const float4 v = sW[buf][w][l + i];
                hE  = fmaf(v.x, KW[i], hE);
                hD  = fmaf(v.y, KW[i], hD);
                hE2 = fmaf(v.z, KW[i], hE2);
                hD2 = fmaf(v.w, KW[i], hD2);
            }
            rE[u] = hE; rD[u] = hD; rE2[u] = hE2; rD2[u] = hD2;

            // vertical conv + SSIM once ring full (output row k-10)
            if (k >= 10) {
                float me = 0.f, md = 0.f, ce2 = 0.f, cd2 = 0.f;
                #pragma unroll
                for (int i = 0; i < 11; i++) {
                    const int s = (u + 1 + i) % 11;
                    me  = fmaf(rE[s],  KW[i], me);
                    md  = fmaf(rD[s],  KW[i], md);
                    ce2 = fmaf(rE2[s], KW[i], ce2);
                    cd2 = fmaf(rD2[s], KW[i], cd2);
                }
                const float A  = me * me;
                const float B  = md * md;
                const float t1 = A - B;
                const float t2 = A + B;
                const float n1 = fmaf(0.5f, t1, C1v);
                const float d1 = fmaf(0.5f, t2, C1v);
                const float n2 = fmaf(0.5f, (ce2 - cd2) - t1, C2v);
                const float d2 = fmaf(0.5f, (ce2 + cd2) - t2, C2v);
                acc += __fdividef(n1 * n2, d1 * d2);
            }
        }
    }

    // deterministic block reduction (one barrier, at the end)
    #pragma unroll
    for (int o = 16; o > 0; o >>= 1)
        acc += __shfl_down_sync(0xffffffffu, acc, o);
    if (l == 0) wsum[w] = acc;
    __syncthreads();
    if (tid < 32) {
        float v = (l < 8) ? wsum[l] : 0.f;
        #pragma unroll
        for (int o = 4; o > 0; o >>= 1)
            v += __shfl_down_sync(0xffffffffu, v, o);
        if (l == 0)
            g_partial[blockIdx.y * (HALVES * STRIPS) + blockIdx.x] = v;
    }

    // deterministic last-block final reduction (fp64, fixed order)
    if (tid == 0) {
        __threadfence();
        const int n = atomicAdd(&g_count, 1);
        sIsLast = (n == NBLK - 1);
    }
    __syncthreads();
    if (sIsLast) {
        __threadfence();
        double s = 0.0;
        for (int i = tid; i < NBLK; i += 256)
            s += (double)g_partial[i];
        dsh[tid] = s;
        __syncthreads();
        #pragma unroll 1
        for (int o = 128; o > 0; o >>= 1) {
            if (tid < o) dsh[tid] += dsh[tid + o];
            __syncthreads();
        }
        if (tid == 0) {
            out[0] = (float)(1.0 - dsh[0] / 25165824.0);  // 32*3*512*512
            g_count = 0;  // reset for next graph replay
        }
    }
}

extern "C" void kernel_launch(void* const* d_in, const int* in_sizes, int n_in,
                              void* d_out, int out_size) {
    const float* pred = (const float*)d_in[0];
    const float* targ = (const float*)d_in[1];
    ssim_main<<<dim3(HALVES * STRIPS, CHANNELS), 256>>>(pred, targ, (float*)d_out);
}

// round 14
// speedup vs baseline: 1.3236x; 1.0959x over previous
#include <cuda_runtime.h>

#define WIDTH    512
#define HEIGHT   512
#define TH       64
#define TH_IN    (TH + 10)            // 74 input rows per strip
#define STRIPS   (HEIGHT / TH)        // 8
#define HALVES   2
#define CHANNELS 96                   // 32 * 3
#define NBLK     (HALVES * STRIPS * CHANNELS) // 1536

#define C1v 1.0e-4f
#define C2v 9.0e-4f

// Gaussian(sigma=1.5, k=11) weights; compile-time indices -> FFMA-imm (rt=1).
#define DECL_KW \
    constexpr float KW[11] = { \
        0.00102838f, 0.00759876f, 0.03600078f, 0.10936081f, 0.21300554f, \
        0.26601173f, \
        0.21300554f, 0.10936081f, 0.03600078f, 0.00759876f, 0.00102838f }

__device__ float g_partial[NBLK];
__device__ int   g_count = 0;

__global__ void __launch_bounds__(256, 4)
ssim_main(const float* __restrict__ pred, const float* __restrict__ targ,
          float* __restrict__ out) {
    DECL_KW;
    // Warp-private staging: 42 (e,d) float2 per warp per buffer
    // (32 own cols + 5 halo each side), double-buffered; only __syncwarp().
    __shared__ float2 sW[2][8][44];
    __shared__ float  wsum[8];
    __shared__ double dsh[256];
    __shared__ int    sIsLast;

    const int tid  = threadIdx.x;
    const int w    = tid >> 5;
    const int l    = tid & 31;
    const int half  = blockIdx.x & 1;
    const int strip = blockIdx.x >> 1;
    const int ch    = blockIdx.y;
    const int y0    = strip * TH;
    const int colbase = half * 256 + w * 32;
    const int c0 = colbase + l;

    // halo assignment for lanes 0..9; clamp address, gate with hval
    int hidx = 0, chalo = c0; bool hval = false;
    if (l < 5)       { chalo = colbase - 5 + l;  hidx = l;      hval = (chalo >= 0); }
    else if (l < 10) { chalo = colbase + 27 + l; hidx = 32 + l; hval = (chalo < WIDTH); }
    if (!hval) chalo = c0;
    const bool isHalo = (l < 10);

    const float* __restrict__ P = pred + (size_t)ch * (WIDTH * HEIGHT);
    const float* __restrict__ T = targ + (size_t)ch * (WIDTH * HEIGHT);

    // vertical ring over 11 horizontal-conv result rows (scalar, 44 regs)
    float rE[11], rD[11], rE2[11], rD2[11];
    float acc = 0.f;

    // unconditional clamped load of row r: FSEL zero-mask, no branches
    #define LOAD_ROW(r, P_, T_, pp, tt, pph, tth) do {                        \
        const int _r  = (r);                                                  \
        const bool _v = ((unsigned)_r < (unsigned)HEIGHT);                    \
        const int _rc = (_r < 0 ? 0 : (_r > HEIGHT - 1 ? HEIGHT - 1 : _r));   \
        const int _ro = _rc * WIDTH;                                          \
        float _p  = (P_)[_ro + c0];                                           \
        float _t  = (T_)[_ro + c0];                                           \
        float _ph = 0.f, _th = 0.f;                                           \
        if (isHalo) { _ph = (P_)[_ro + chalo]; _th = (T_)[_ro + chalo]; }     \
        (pp)  = _v ? _p : 0.f;                                                \
        (tt)  = _v ? _t : 0.f;                                                \
        (pph) = (_v && hval) ? _ph : 0.f;                                     \
        (tth) = (_v && hval) ? _th : 0.f;                                     \
    } while (0)

    // 1-deep prefetch (row k=0, abs y0-5)
    float pN, tN, pHN, tHN;
    LOAD_ROW(y0 - 5, P, T, pN, tN, pHN, tHN);

    // k = 0..TH_IN-1; ring slot = k % 11 (kc % 11 == 0 keeps it compile-time)
    #pragma unroll 1
    for (int kc = 0; kc < TH_IN; kc += 11) {
        #pragma unroll
        for (int u = 0; u < 11; u++) {
            const int k = kc + u;
            if (k >= TH_IN) break;   // uniform

            const float p = pN, t = tN, ph = pHN, th = tHN;
            // unconditional prefetch of row k+1 (abs y0-4+k); clamped+masked
            LOAD_ROW(y0 - 4 + k, P, T, pN, tN, pHN, tHN);

            // stage (e,d); warp-private, so only syncwarp needed
            const int buf = k & 1;
            sW[buf][w][5 + l] = make_float2(p + t, p - t);
            if (isHalo) sW[buf][w][hidx] = make_float2(ph + th, ph - th);
            __syncwarp();

            // horizontal conv: 11 LDS.64 + 22 FMUL + 44 FFMA-imm
            float hE = 0.f, hD = 0.f, hE2 = 0.f, hD2 = 0.f;
            #pragma unroll
            for (int i = 0; i < 11; i++) {
                const float2 v = sW[buf][w][l + i];
                hE  = fmaf(v.x,       KW[i], hE);
                hD  = fmaf(v.y,       KW[i], hD);
                hE2 = fmaf(v.x * v.x, KW[i], hE2);
                hD2 = fmaf(v.y * v.y, KW[i], hD2);
            }
            rE[u] = hE; rD[u] = hD; rE2[u] = hE2; rD2[u] = hD2;

            // vertical conv + SSIM once ring full (output row k-10)
            if (k >= 10) {
                float me = 0.f, md = 0.f, ce2 = 0.f, cd2 = 0.f;
                #pragma unroll
                for (int i = 0; i < 11; i++) {
                    const int s = (u + 1 + i) % 11;
                    me  = fmaf(rE[s],  KW[i], me);
                    md  = fmaf(rD[s],  KW[i], md);
                    ce2 = fmaf(rE2[s], KW[i], ce2);
                    cd2 = fmaf(rD2[s], KW[i], cd2);
                }
                const float A  = me * me;
                const float B  = md * md;
                const float t1 = A - B;
                const float t2 = A + B;
                const float n1 = fmaf(0.5f, t1, C1v);
                const float d1 = fmaf(0.5f, t2, C1v);
                const float n2 = fmaf(0.5f, (ce2 - cd2) - t1, C2v);
                const float d2 = fmaf(0.5f, (ce2 + cd2) - t2, C2v);
                acc += __fdividef(n1 * n2, d1 * d2);
            }
        }
    }

    // deterministic block reduction (one barrier, at the end)
    #pragma unroll
    for (int o = 16; o > 0; o >>= 1)
        acc += __shfl_down_sync(0xffffffffu, acc, o);
    if (l == 0) wsum[w] = acc;
    __syncthreads();
    if (tid < 32) {
        float v = (l < 8) ? wsum[l] : 0.f;
        #pragma unroll
        for (int o = 4; o > 0; o >>= 1)
            v += __shfl_down_sync(0xffffffffu, v, o);
        if (l == 0)
            g_partial[blockIdx.y * (HALVES * STRIPS) + blockIdx.x] = v;
    }

    // deterministic last-block final reduction (fp64, fixed order)
    if (tid == 0) {
        __threadfence();
        const int n = atomicAdd(&g_count, 1);
        sIsLast = (n == NBLK - 1);
    }
    __syncthreads();
    if (sIsLast) {
        __threadfence();
        double s = 0.0;
        for (int i = tid; i < NBLK; i += 256)
            s += (double)g_partial[i];
        dsh[tid] = s;
        __syncthreads();
        #pragma unroll 1
        for (int o = 128; o > 0; o >>= 1) {
            if (tid < o) dsh[tid] += dsh[tid + o];
            __syncthreads();
        }
        if (tid == 0) {
            out[0] = (float)(1.0 - dsh[0] / 25165824.0);  // 32*3*512*512
            g_count = 0;  // reset for next graph replay
        }
    }
}

extern "C" void kernel_launch(void* const* d_in, const int* in_sizes, int n_in,
                              void* d_out, int out_size) {
    const float* pred = (const float*)d_in[0];
    const float* targ = (const float*)d_in[1];
    ssim_main<<<dim3(HALVES * STRIPS, CHANNELS), 256>>>(pred, targ, (float*)d_out);
}